// round 17
// baseline (speedup 1.0000x reference)
#include <cuda_runtime.h>
#include <cuda_fp16.h>
#include <cstdint>
#include <math.h>

#define HW    9216
#define CH    256
#define NB    2

// ---------------- scratch ----------------
__device__ float g_f[8ull * 9 * HW];               // [nb][o][HW] softmax tap weights
__device__ float g_u[(size_t)NB * 384 * HW];       // [n][br*96 + o*9+tap][HW]
__device__ __half g_z[10ull * HW * CH + 400000];   // [b*2+n][p][c]  fp16
__device__ __half g_y[(size_t)NB * HW * CH];       // [n][p][c] fp16
__device__ float g_bpart[NB * 1152 * 64];
__device__ float g_stats[NB * 32 * 2];
__device__ __half g_w[5ull * 256 * 256];           // [b][m][c] fp16(w)
__device__ __half g_xT[(size_t)NB * HW * 256];     // [n][p][c] fp16(x)
__device__ __half g_wl2[384ull * 256];             // [m][c] fp16 logits weights

// ---------------- helpers ----------------
__device__ __forceinline__ uint32_t smem_u32(const void* p) {
    uint32_t a;
    asm("{ .reg .u64 t; cvta.to.shared.u64 t, %1; cvt.u32.u64 %0, t; }" : "=r"(a) : "l"(p));
    return a;
}
__device__ __forceinline__ void ldmatrix_x4(uint32_t& r0, uint32_t& r1, uint32_t& r2, uint32_t& r3, uint32_t addr) {
    asm volatile("ldmatrix.sync.aligned.m8n8.x4.shared.b16 {%0,%1,%2,%3}, [%4];"
        : "=r"(r0), "=r"(r1), "=r"(r2), "=r"(r3) : "r"(addr));
}
__device__ __forceinline__ void mma_f16(float* c, const uint32_t* a, uint32_t b0, uint32_t b1) {
    asm volatile("mma.sync.aligned.m16n8k16.row.col.f32.f16.f16.f32 "
        "{%0,%1,%2,%3}, {%4,%5,%6,%7}, {%8,%9}, {%0,%1,%2,%3};"
        : "+f"(c[0]), "+f"(c[1]), "+f"(c[2]), "+f"(c[3])
        : "r"(a[0]), "r"(a[1]), "r"(a[2]), "r"(a[3]), "r"(b0), "r"(b1));
}
__device__ __forceinline__ void cp_async16(uint32_t saddr, const void* gaddr) {
    asm volatile("cp.async.cg.shared.global [%0], [%1], 16;" :: "r"(saddr), "l"(gaddr));
}

// ---------------- prep: W (proj) -> fp16 ----------------
__global__ void __launch_bounds__(256) wsplit_kernel(const float* __restrict__ wproj)
{
    int idx = blockIdx.x * 256 + threadIdx.x;
    if (idx >= 5 * 65536) return;
    int b = idx >> 16, rem = idx & 65535;
    int m = rem >> 8, c = rem & 255;
    g_w[((size_t)b * 256 + m) * 256 + c] = __float2half(wproj[m * 1280 + b * 256 + c]);
}

// ---------------- prep: logits weights -> A[384][256] fp16 ----------------
__global__ void __launch_bounds__(256) wl2split_kernel(
    const float* __restrict__ wa, const float* __restrict__ wb,
    const float* __restrict__ wc, const float* __restrict__ wd)
{
    int idx = blockIdx.x * 256 + threadIdx.x;       // 384*256
    if (idx >= 98304) return;
    int c = idx & 255, m = idx >> 8;
    int br = m / 96, row = m - br * 96;
    float w = 0.f;
    if (row < 81) {
        int o = row / 9, tap = row - o * 9;
        const float* wp = (br == 0) ? wa : (br == 1) ? wb : (br == 2) ? wc : wd;
        w = wp[(o * 256 + c) * 9 + tap];
    }
    g_wl2[(size_t)m * 256 + c] = __float2half(w);
}

// ---------------- prep: transpose x to [p][c] fp16 ----------------
__global__ void __launch_bounds__(256) xsplit_kernel(const float* __restrict__ x)
{
    __shared__ float t[32][33];
    int p0 = blockIdx.x * 32, k0 = blockIdx.y * 32, n = blockIdx.z;
    int tx = threadIdx.x, ty = threadIdx.y;
#pragma unroll
    for (int r = 0; r < 4; r++)
        t[ty + 8 * r][tx] = x[((size_t)(n * 256 + k0 + ty + 8 * r)) * HW + p0 + tx];
    __syncthreads();
#pragma unroll
    for (int r = 0; r < 4; r++) {
        int p = p0 + ty + 8 * r, c = k0 + tx;
        g_xT[((size_t)n * HW + p) * 256 + c] = __float2half(t[tx][ty + 8 * r]);
    }
}

// ================= GEMM tile: 128m x 128p; 4 warps of 64m x 64p =============
// K=256 in 4 chunks of 64; smem stage 32KB (A 16 + B 16), 3 stages = 96KB; 2 CTA/SM
struct MmaCtx {
    uint32_t sbase;
    int tid, lane, warp_m, warp_n;
    float acc[4][8][4];
    __device__ __forceinline__ void init(uint32_t sb, int t) {
        sbase = sb; tid = t; lane = t & 31;
        int wid = t >> 5;             // 0..3
        warp_m = wid & 1; warp_n = wid >> 1;
#pragma unroll
        for (int i = 0; i < 4; i++)
#pragma unroll
            for (int j = 0; j < 8; j++)
#pragma unroll
                for (int r = 0; r < 4; r++) acc[i][j][r] = 0.f;
    }
    __device__ __forceinline__ void fill(int buf, const char* Ag, const char* Bg) {
        uint32_t aOff = buf * 32768u;
        uint32_t bOff = 16384u + buf * 32768u;
#pragma unroll
        for (int r = 0; r < 8; r++) {
            int idx = tid + 128 * r;          // 0..1023 : row(128) x u(8)
            int row = idx >> 3, u = idx & 7;
            uint32_t sw = row * 128 + ((u ^ (row & 7)) << 4);
            cp_async16(sbase + aOff + sw, Ag + (size_t)row * 512 + u * 16);
            cp_async16(sbase + bOff + sw, Bg + (size_t)row * 512 + u * 16);
        }
        asm volatile("cp.async.commit_group;");
    }
    __device__ __forceinline__ void compute(int buf) {
        uint32_t aB = sbase + buf * 32768u;
        uint32_t bB = sbase + 16384u + buf * 32768u;
#pragma unroll
        for (int ks = 0; ks < 4; ks++) {
            int u0 = ks * 2 + (lane >> 4);
            uint32_t a[4][4], bb[4][4];
#pragma unroll
            for (int q = 0; q < 4; q++) {
                int row = warp_n * 64 + q * 16 + (lane & 15);
                ldmatrix_x4(bb[q][0], bb[q][1], bb[q][2], bb[q][3],
                            bB + row * 128 + (((unsigned)(u0 ^ (row & 7))) << 4));
            }
#pragma unroll
            for (int mi = 0; mi < 4; mi++) {
                int row = warp_m * 64 + mi * 16 + (lane & 15);
                ldmatrix_x4(a[mi][0], a[mi][1], a[mi][2], a[mi][3],
                            aB + row * 128 + (((unsigned)(u0 ^ (row & 7))) << 4));
            }
#pragma unroll
            for (int mi = 0; mi < 4; mi++)
#pragma unroll
                for (int nj = 0; nj < 8; nj++) {
                    int q = nj >> 1, pr = nj & 1;
                    mma_f16(acc[mi][nj], a[mi], bb[q][pr], bb[q][pr + 2]);
                }
        }
    }
    __device__ __forceinline__ void run(const char* Abase, const char* Bbase) {
        fill(0, Abase, Bbase);
        fill(1, Abase + 128, Bbase + 128);
        for (int i = 0; i < 4; i++) {
            if (i < 3) asm volatile("cp.async.wait_group 1;");
            else       asm volatile("cp.async.wait_group 0;");
            __syncthreads();
            compute(i % 3);
            if (i + 2 < 4) fill((i + 2) % 3, Abase + (i + 2) * 128, Bbase + (i + 2) * 128);
        }
        __syncthreads();
    }
    __device__ __forceinline__ void stage_out(float* stage) {
#pragma unroll
        for (int mi = 0; mi < 4; mi++)
#pragma unroll
            for (int nj = 0; nj < 8; nj++)
#pragma unroll
                for (int r = 0; r < 4; r++) {
                    int p = warp_n * 64 + nj * 8 + 2 * (lane & 3) + (r & 1);
                    int m = warp_m * 64 + mi * 16 + (lane >> 2) + ((r >> 1) << 3);
                    stage[p * 132 + m] = acc[mi][nj][r];
                }
    }
};

// ---------------- 1+3) merged GEMM: grid (72, 13, 2), block 128 ----------------
// y 0..2  : U-tile  -> g_u[m][p] fp32 ;  y 3..12 : proj -> g_z fp16
__global__ void __launch_bounds__(128, 2) gemm_all_kernel()
{
    extern __shared__ char dsm[];
    MmaCtx g;
    g.init(smem_u32(dsm), threadIdx.x);
    int pbase = blockIdx.x * 128;
    int iy = blockIdx.y;
    int n = blockIdx.z;

    const char* Bsrc = (const char*)g_xT + ((size_t)n * HW + pbase) * 512;
    float* stage = (float*)dsm;

    if (iy < 3) {
        int mbase = iy * 128;
        g.run((const char*)g_wl2 + (size_t)mbase * 512, Bsrc);
        g.stage_out(stage);
        __syncthreads();
#pragma unroll
        for (int rr = 0; rr < 32; rr++) {
            int idx = threadIdx.x + 128 * rr;      // 0..4095
            int m = idx >> 5, p4 = (idx & 31) * 4;
            float4 v = make_float4(stage[p4 * 132 + m], stage[(p4 + 1) * 132 + m],
                                   stage[(p4 + 2) * 132 + m], stage[(p4 + 3) * 132 + m]);
            *(float4*)(g_u + ((size_t)n * 384 + mbase + m) * HW + pbase + p4) = v;
        }
    } else {
        int idx2 = iy - 3;
        int b = idx2 >> 1, mh = idx2 & 1;
        int mbase = mh * 128;
        g.run((const char*)g_w + ((size_t)b * 256 + mbase) * 512, Bsrc);
        g.stage_out(stage);
        __syncthreads();
        __half* zo = g_z + ((size_t)(b * 2 + n) * HW + pbase) * 256 + mbase;
#pragma unroll
        for (int r = 0; r < 32; r++) {
            int idx = threadIdx.x + 128 * r;       // 0..4095
            int px = idx >> 5, c4 = (idx & 31) * 4;
            float4 v = *(float4*)&stage[px * 132 + c4];
            __half2 lo = __floats2half2_rn(v.x, v.y);
            __half2 hi = __floats2half2_rn(v.z, v.w);
            uint2 pk;
            pk.x = *(uint32_t*)&lo;
            pk.y = *(uint32_t*)&hi;
            *(uint2*)(zo + (size_t)px * 256 + c4) = pk;
        }
    }
}

// ---------------- 2) gather taps + softmax ----------------
__global__ void __launch_bounds__(256) gathersoftmax_kernel()
{
    int id = blockIdx.x * 256 + threadIdx.x;
    int p = id % HW;
    int nb = id / HW;
    int n = nb >> 2, br = nb & 3;
    int d = (br == 0) ? 1 : (br == 1) ? 4 : (br == 2) ? 8 : 12;
    int y = p / 96, x = p - y * 96;

    int po[9];
#pragma unroll
    for (int t = 0; t < 9; t++) {
        int yy = y + (t / 3 - 1) * d;
        int xx = x + (t % 3 - 1) * d;
        po[t] = (((unsigned)yy < 96u) && ((unsigned)xx < 96u)) ? (yy * 96 + xx) : -1;
    }

    const float* ub = g_u + ((size_t)n * 384 + br * 96) * HW;
    float l[9];
#pragma unroll
    for (int o = 0; o < 9; o++) {
        float s = 0.f;
#pragma unroll
        for (int t = 0; t < 9; t++)
            if (po[t] >= 0) s += ub[(size_t)(o * 9 + t) * HW + po[t]];
        l[o] = s;
    }
    float m = l[0];
#pragma unroll
    for (int o = 1; o < 9; o++) m = fmaxf(m, l[o]);
    float s = 0.f;
#pragma unroll
    for (int o = 0; o < 9; o++) { l[o] = expf(l[o] - m); s += l[o]; }
    float inv = 1.f / s;
#pragma unroll
    for (int o = 0; o < 9; o++)
        g_f[((size_t)nb * 9 + o) * HW + p] = l[o] * inv;
}

// ---------------- 4) combine: one warp per pixel, fp16 z, fp16 y ----------------
__global__ void __launch_bounds__(512) combine_kernel(const float* __restrict__ bias)
{
    int tid = threadIdx.x;
    int n = blockIdx.y;
    int p0 = blockIdx.x * 16;
    int warp = tid >> 5, lane = tid & 31;
    int p = p0 + warp;
    int c8 = lane * 8;

    __shared__ float fsw[16][40];
    __shared__ int   pofs[16][40];
    __shared__ float ws[16][32];
    __shared__ float wq[16][32];

    for (int i = tid; i < 16 * 36; i += 512) {
        int pi2 = i / 36, j = i - pi2 * 36;
        int br = j / 9, k = j - br * 9;
        int d = (br == 0) ? 1 : (br == 1) ? 4 : (br == 2) ? 8 : 12;
        int pg = p0 + pi2;
        int yy = pg / 96 + (k / 3 - 1) * d;
        int xx = pg % 96 + (k % 3 - 1) * d;
        bool v = ((unsigned)yy < 96u) && ((unsigned)xx < 96u);
        fsw[pi2][j]  = v ? g_f[((size_t)(n * 4 + br) * 9 + k) * HW + pg] : 0.f;
        pofs[pi2][j] = (((br + 1) * 2 + n) * HW + (v ? (yy * 96 + xx) : 0)) * 256;
    }
    __syncthreads();

    float a[8];
    {
        float4 b0 = *(const float4*)(bias + c8);
        float4 b1 = *(const float4*)(bias + c8 + 4);
        uint4 zv = *(const uint4*)(g_z + ((size_t)n * HW + p) * 256 + c8);
        float2 f0 = __half22float2(*(__half2*)&zv.x);
        float2 f1 = __half22float2(*(__half2*)&zv.y);
        float2 f2 = __half22float2(*(__half2*)&zv.z);
        float2 f3 = __half22float2(*(__half2*)&zv.w);
        a[0] = f0.x + b0.x; a[1] = f0.y + b0.y; a[2] = f1.x + b0.z; a[3] = f1.y + b0.w;
        a[4] = f2.x + b1.x; a[5] = f2.y + b1.y; a[6] = f3.x + b1.z; a[7] = f3.y + b1.w;
    }

#pragma unroll 4
    for (int j = 0; j < 36; j++) {
        float f = fsw[warp][j];
        uint4 zv = *(const uint4*)(g_z + (size_t)pofs[warp][j] + c8);
        float2 f0 = __half22float2(*(__half2*)&zv.x);
        float2 f1 = __half22float2(*(__half2*)&zv.y);
        float2 f2 = __half22float2(*(__half2*)&zv.z);
        float2 f3 = __half22float2(*(__half2*)&zv.w);
        a[0] = fmaf(f, f0.x, a[0]); a[1] = fmaf(f, f0.y, a[1]);
        a[2] = fmaf(f, f1.x, a[2]); a[3] = fmaf(f, f1.y, a[3]);
        a[4] = fmaf(f, f2.x, a[4]); a[5] = fmaf(f, f2.y, a[5]);
        a[6] = fmaf(f, f3.x, a[6]); a[7] = fmaf(f, f3.y, a[7]);
    }

    {
        __half2 h0 = __floats2half2_rn(a[0], a[1]);
        __half2 h1 = __floats2half2_rn(a[2], a[3]);
        __half2 h2 = __floats2half2_rn(a[4], a[5]);
        __half2 h3 = __floats2half2_rn(a[6], a[7]);
        uint4 pk;
        pk.x = *(uint32_t*)&h0; pk.y = *(uint32_t*)&h1;
        pk.z = *(uint32_t*)&h2; pk.w = *(uint32_t*)&h3;
        *(uint4*)(g_y + ((size_t)n * HW + p) * 256 + c8) = pk;
    }

    float s = a[0] + a[1] + a[2] + a[3] + a[4] + a[5] + a[6] + a[7];
    float q = a[0]*a[0] + a[1]*a[1] + a[2]*a[2] + a[3]*a[3]
            + a[4]*a[4] + a[5]*a[5] + a[6]*a[6] + a[7]*a[7];
    ws[warp][lane] = s;
    wq[warp][lane] = q;
    __syncthreads();

    if (tid < 64) {
        int g = tid >> 1, isq = tid & 1;
        float acc = 0.f;
#pragma unroll
        for (int w = 0; w < 16; w++)
            acc += isq ? wq[w][g] : ws[w][g];
        g_bpart[((size_t)n * 576 + blockIdx.x) * 64 + tid] = acc;
    }
}

// ---------------- 5) GN stats ----------------
__global__ void __launch_bounds__(128) stats_kernel()
{
    int b = blockIdx.x;
    int n = b >> 5, g = b & 31;
    int tid = threadIdx.x;
    float s = 0.f, q = 0.f;
    for (int i = tid; i < 576; i += 128) {
        size_t base = ((size_t)n * 576 + i) * 64 + g * 2;
        s += g_bpart[base];
        q += g_bpart[base + 1];
    }
    __shared__ float ss[128], sq[128];
    ss[tid] = s; sq[tid] = q;
    __syncthreads();
    for (int off = 64; off > 0; off >>= 1) {
        if (tid < off) { ss[tid] += ss[tid + off]; sq[tid] += sq[tid + off]; }
        __syncthreads();
    }
    if (tid == 0) {
        const float invN = 1.f / 73728.f;
        float mean = ss[0] * invN;
        float var  = sq[0] * invN - mean * mean;
        g_stats[b * 2]     = mean;
        g_stats[b * 2 + 1] = rsqrtf(var + 1e-5f);
    }
}

// ---------------- 6) transpose + GN affine + relu (fp16 y in) ----------------
__global__ void __launch_bounds__(256) normT_kernel(
    const float* __restrict__ gamma, const float* __restrict__ beta,
    float* __restrict__ out)
{
    __shared__ float t[32][33];
    int p0 = blockIdx.x * 32, c0 = blockIdx.y * 32, n = blockIdx.z;
    int tx = threadIdx.x, ty = threadIdx.y;
#pragma unroll
    for (int r = 0; r < 4; r++)
        t[ty + 8 * r][tx] = __half2float(g_y[((size_t)n * HW + p0 + ty + 8 * r) * 256 + c0 + tx]);
    __syncthreads();
#pragma unroll
    for (int r = 0; r < 4; r++) {
        int c = c0 + ty + 8 * r, p = p0 + tx;
        int g = c >> 3;
        float mean = g_stats[(n * 32 + g) * 2];
        float rstd = g_stats[(n * 32 + g) * 2 + 1];
        float ga = gamma[c] * rstd;
        float be = beta[c] - mean * ga;
        float v = t[tx][ty + 8 * r];
        out[((size_t)n * 256 + c) * HW + p] = fmaxf(fmaf(v, ga, be), 0.f);
    }
}

// ---------------- launch ----------------
extern "C" void kernel_launch(void* const* d_in, const int* in_sizes, int n_in,
                              void* d_out, int out_size)
{
    const float* x     = (const float*)d_in[0];
    const float* wa    = (const float*)d_in[1];
    const float* wb    = (const float*)d_in[2];
    const float* wc    = (const float*)d_in[3];
    const float* wd    = (const float*)d_in[4];
    const float* wproj = (const float*)d_in[5];
    const float* bproj = (const float*)d_in[6];
    const float* gamma = (const float*)d_in[7];
    const float* beta  = (const float*)d_in[8];
    float* out = (float*)d_out;

    cudaFuncSetAttribute(gemm_all_kernel, cudaFuncAttributeMaxDynamicSharedMemorySize, 98304);

    wsplit_kernel<<<1280, 256>>>(wproj);
    wl2split_kernel<<<384, 256>>>(wa, wb, wc, wd);
    xsplit_kernel<<<dim3(288, 8, 2), dim3(32, 8)>>>(x);
    gemm_all_kernel<<<dim3(72, 13, 2), 128, 98304>>>();
    gathersoftmax_kernel<<<288, 256>>>();
    combine_kernel<<<dim3(576, 2), 512>>>(bproj);
    stats_kernel<<<64, 128>>>();
    normT_kernel<<<dim3(288, 8, 2), dim3(32, 8)>>>(gamma, beta, out);
}